// round 7
// baseline (speedup 1.0000x reference)
#include <cuda_runtime.h>

#define TPB 256
#define MAX_BLOCKS 4096

__device__ float g_partials[MAX_BLOCKS];

__device__ __forceinline__ float compute_iou(float bx, float by, float bw, float bh,
                                             float lx, float ly, float lw, float lh) {
    const float invS = 1.0f / 7.0f;
    float x1 = bx * invS - bw * 0.5f;
    float y1 = by * invS - bh * 0.5f;
    float x2 = bx * invS + bw * 0.5f;
    float y2 = by * invS + bh * 0.5f;
    float u1 = lx * invS - lw * 0.5f;
    float v1 = ly * invS - lh * 0.5f;
    float u2 = lx * invS + lw * 0.5f;
    float v2 = ly * invS + lh * 0.5f;
    float a1 = (x2 - x1) * (y2 - y1);
    float a2 = (u2 - u1) * (v2 - v1);
    float left   = fmaxf(x1, u1);
    float right  = fminf(x2, u2);
    float top    = fmaxf(y1, v1);
    float bottom = fminf(y2, v2);
    bool valid = (left < right) && (top < bottom);
    float inter = valid ? (right - left) * (bottom - top) : 0.0f;
    float uni = a1 + a2 - inter;
    return valid ? (inter / uni) : 0.0f;
}

// Full loss terms for a coord cell, MINUS the 0.5*(p4^2+p9^2) already counted
// by the streaming conf accumulation.
__device__ __noinline__ float coord_cell_extra(const float* __restrict__ predict,
                                               const float* __restrict__ label,
                                               int cell) {
    const float2* pp = reinterpret_cast<const float2*>(predict + (size_t)cell * 26);
    const float2* lp = reinterpret_cast<const float2*>(label   + (size_t)cell * 26);

    float2 p01 = __ldg(pp + 0);
    float2 p23 = __ldg(pp + 1);
    float2 p45 = __ldg(pp + 2);
    float2 p67 = __ldg(pp + 3);
    float2 p89 = __ldg(pp + 4);
    float2 l01 = __ldg(lp + 0);
    float2 l23 = __ldg(lp + 1);

    float cls = 0.0f;
#pragma unroll
    for (int j = 5; j < 13; j++) {
        float2 pv = __ldg(pp + j);
        float2 lv = __ldg(lp + j);
        float dx = pv.x - lv.x;
        float dy = pv.y - lv.y;
        cls += dx * dx + dy * dy;
    }

    float iou1 = compute_iou(p01.x, p01.y, p23.x, p23.y, l01.x, l01.y, l23.x, l23.y);
    float iou2 = compute_iou(p45.y, p67.x, p67.y, p89.x, l01.x, l01.y, l23.x, l23.y);
    bool pick1 = iou1 > iou2;

    float s0 = pick1 ? p01.x : p45.y;
    float s1 = pick1 ? p01.y : p67.x;
    float s2 = pick1 ? p23.x : p67.y;
    float s3 = pick1 ? p23.y : p89.x;

    float d0 = s0 - l01.x;
    float d1 = s1 - l01.y;
    float d2 = sqrtf(s2) - sqrtf(l23.x);
    float d3 = sqrtf(s3) - sqrtf(l23.y);
    float coord_cell = d0 * d0 + d1 * d1 + d2 * d2 + d3 * d3;

    float p4 = p45.x, p9 = p89.y;
    float c  = pick1 ? p4 : p9;
    float io = pick1 ? iou1 : iou2;
    float dc = c - io;
    float obj_c = dc * dc;

    float other = pick1 ? p9 : p4;

    // + coord terms + obj + 0.5*other^2, and remove the streamed 0.5*(p4^2+p9^2)
    return 5.0f * coord_cell + obj_c + cls
           + 0.5f * (other * other - p4 * p4 - p9 * p9);
}

// Streaming pass: coalesced float4 over predict. 2 cells == 13 float4s.
// m = i % 13 gives position: m==1 -> elem.x = p4(cell0); m==2 -> elem.y = p9(cell0);
// m==7 -> elem.z = p4(cell1); m==8 -> elem.w = p9(cell1).
// Label is touched only at the two l4 positions (m==1 elem.x, m==7 elem.z).
__global__ void __launch_bounds__(TPB)
yolo_stream_kernel(const float* __restrict__ predict,
                   const float* __restrict__ label,
                   int nf4) {
    const int tid = threadIdx.x;
    int idx = blockIdx.x * TPB + tid;
    const int step = gridDim.x * TPB;
    const float4* P4 = reinterpret_cast<const float4*>(predict);

    float loss = 0.0f;

    for (int i = idx; i < nf4; i += step) {
        float4 pv = __ldg(P4 + i);
        unsigned int q = (unsigned int)i / 13u;   // cell pair index
        unsigned int m = (unsigned int)i - q * 13u;

        if (m == 1u) {
            loss += 0.5f * pv.x * pv.x;           // p4 of cell 2q
            float l4 = __ldg(label + (size_t)(2u * q) * 26 + 4);
            if (l4 > 0.0f)
                loss += coord_cell_extra(predict, label, 2 * (int)q);
        } else if (m == 2u) {
            loss += 0.5f * pv.y * pv.y;           // p9 of cell 2q
        } else if (m == 7u) {
            loss += 0.5f * pv.z * pv.z;           // p4 of cell 2q+1
            float l4 = __ldg(label + (size_t)(2u * q + 1u) * 26 + 4);
            if (l4 > 0.0f)
                loss += coord_cell_extra(predict, label, 2 * (int)q + 1);
        } else if (m == 8u) {
            loss += 0.5f * pv.w * pv.w;           // p9 of cell 2q+1
        }
    }

    // ---- block reduction ----
    __shared__ float sm[TPB / 32];
    float s = loss;
#pragma unroll
    for (int o = 16; o > 0; o >>= 1)
        s += __shfl_down_sync(0xFFFFFFFFu, s, o);
    if ((tid & 31) == 0)
        sm[tid >> 5] = s;
    __syncthreads();
    if (tid < 32) {
        s = (tid < (TPB / 32)) ? sm[tid] : 0.0f;
#pragma unroll
        for (int o = 16; o > 0; o >>= 1)
            s += __shfl_down_sync(0xFFFFFFFFu, s, o);
        if (tid == 0)
            g_partials[blockIdx.x] = s;
    }
}

__global__ void yolo_reduce_kernel(float* __restrict__ out, int nblocks, float invN) {
    __shared__ float sm[16];
    float s = 0.0f;
    for (int i = threadIdx.x; i < nblocks; i += blockDim.x)
        s += g_partials[i];
#pragma unroll
    for (int o = 16; o > 0; o >>= 1)
        s += __shfl_down_sync(0xFFFFFFFFu, s, o);
    if ((threadIdx.x & 31) == 0)
        sm[threadIdx.x >> 5] = s;
    __syncthreads();
    if (threadIdx.x < 32) {
        s = (threadIdx.x < (int)(blockDim.x >> 5)) ? sm[threadIdx.x] : 0.0f;
#pragma unroll
        for (int o = 16; o > 0; o >>= 1)
            s += __shfl_down_sync(0xFFFFFFFFu, s, o);
        if (threadIdx.x == 0)
            out[0] = s * invN;
    }
}

extern "C" void kernel_launch(void* const* d_in, const int* in_sizes, int n_in,
                              void* d_out, int out_size) {
    const float* predict = (const float*)d_in[0];
    const float* label   = (const float*)d_in[1];
    float* out = (float*)d_out;

    int total  = in_sizes[0];          // B*7*7*26 floats
    int ncells = total / 26;           // B*49
    int nf4 = total / 4;               // float4 count (26*ncells divisible by 4: ncells even)

    // ~8 float4s per thread
    int nblocks = (nf4 + TPB * 8 - 1) / (TPB * 8);
    if (nblocks > MAX_BLOCKS) nblocks = MAX_BLOCKS;

    float invN = 49.0f / (float)ncells;  // 1 / batch

    yolo_stream_kernel<<<nblocks, TPB>>>(predict, label, nf4);
    yolo_reduce_kernel<<<1, 512>>>(out, nblocks, invN);
}

// round 8
// speedup vs baseline: 2.2807x; 2.2807x over previous
#include <cuda_runtime.h>

#define TPB 256
#define MAX_BLOCKS 8192

__device__ float g_partials[MAX_BLOCKS];

__device__ __forceinline__ float compute_iou(float bx, float by, float bw, float bh,
                                             float lx, float ly, float lw, float lh) {
    const float invS = 1.0f / 7.0f;
    float x1 = bx * invS - bw * 0.5f;
    float y1 = by * invS - bh * 0.5f;
    float x2 = bx * invS + bw * 0.5f;
    float y2 = by * invS + bh * 0.5f;
    float u1 = lx * invS - lw * 0.5f;
    float v1 = ly * invS - lh * 0.5f;
    float u2 = lx * invS + lw * 0.5f;
    float v2 = ly * invS + lh * 0.5f;
    float a1 = (x2 - x1) * (y2 - y1);
    float a2 = (u2 - u1) * (v2 - v1);
    float left   = fmaxf(x1, u1);
    float right  = fminf(x2, u2);
    float top    = fmaxf(y1, v1);
    float bottom = fminf(y2, v2);
    bool valid = (left < right) && (top < bottom);
    float inter = valid ? (right - left) * (bottom - top) : 0.0f;
    float uni = a1 + a2 - inter;
    return valid ? (inter / uni) : 0.0f;
}

__global__ void __launch_bounds__(TPB)
yolo_cell_kernel(const float* __restrict__ predict,
                 const float* __restrict__ label,
                 int ncells) {
    int cell = blockIdx.x * blockDim.x + threadIdx.x;
    float loss = 0.0f;

    if (cell < ncells) {
        const float* pbase = predict + (size_t)cell * 26;
        const float* lbase = label   + (size_t)cell * 26;

        float l4 = __ldg(lbase + 4);
        float p4 = __ldg(pbase + 4);
        float p9 = __ldg(pbase + 9);

        if (l4 == 0.0f) {
            // noobj cell (~96%)
            loss = 0.5f * (p4 * p4 + p9 * p9);
        } else {
            // coord cell (~4%) — float2 streaming, no local arrays, no spills
            const float2* pp = reinterpret_cast<const float2*>(pbase);
            const float2* lp = reinterpret_cast<const float2*>(lbase);

            float2 p01 = __ldg(pp + 0);
            float2 p23 = __ldg(pp + 1);
            float2 p45 = __ldg(pp + 2);
            float2 p67 = __ldg(pp + 3);
            float2 p89 = __ldg(pp + 4);
            float2 l01 = __ldg(lp + 0);
            float2 l23 = __ldg(lp + 1);

            float cls = 0.0f;
#pragma unroll
            for (int j = 5; j < 13; j++) {
                float2 pv = __ldg(pp + j);
                float2 lv = __ldg(lp + j);
                float dx = pv.x - lv.x;
                float dy = pv.y - lv.y;
                cls += dx * dx + dy * dy;
            }

            float iou1 = compute_iou(p01.x, p01.y, p23.x, p23.y,
                                     l01.x, l01.y, l23.x, l23.y);
            float iou2 = compute_iou(p45.y, p67.x, p67.y, p89.x,
                                     l01.x, l01.y, l23.x, l23.y);
            bool pick1 = iou1 > iou2;

            float s0 = pick1 ? p01.x : p45.y;
            float s1 = pick1 ? p01.y : p67.x;
            float s2 = pick1 ? p23.x : p67.y;
            float s3 = pick1 ? p23.y : p89.x;

            float d0 = s0 - l01.x;
            float d1 = s1 - l01.y;
            float d2 = sqrtf(s2) - sqrtf(l23.x);
            float d3 = sqrtf(s3) - sqrtf(l23.y);
            float coord_cell = d0 * d0 + d1 * d1 + d2 * d2 + d3 * d3;

            float c  = pick1 ? p45.x : p89.y;
            float io = pick1 ? iou1  : iou2;
            float dc = c - io;
            float obj_c_cell = dc * dc;

            float other = pick1 ? p89.y : p45.x;
            float noobj_extra = other * other;

            loss = 5.0f * coord_cell + obj_c_cell + 0.5f * noobj_extra + cls;
        }
    }

    // ---- block reduction ----
    __shared__ float sm[TPB / 32];
    float s = loss;
#pragma unroll
    for (int o = 16; o > 0; o >>= 1)
        s += __shfl_down_sync(0xFFFFFFFFu, s, o);
    if ((threadIdx.x & 31) == 0)
        sm[threadIdx.x >> 5] = s;
    __syncthreads();
    if (threadIdx.x < 32) {
        s = (threadIdx.x < (TPB / 32)) ? sm[threadIdx.x] : 0.0f;
#pragma unroll
        for (int o = 16; o > 0; o >>= 1)
            s += __shfl_down_sync(0xFFFFFFFFu, s, o);
        if (threadIdx.x == 0)
            g_partials[blockIdx.x] = s;
    }
}

__global__ void yolo_reduce_kernel(float* __restrict__ out, int nblocks, float invN) {
    // PDL: this kernel's launch overlaps the producer; block here until the
    // producer grid has fully completed (its partial writes are then visible).
    cudaGridDependencySynchronize();

    __shared__ float sm[32];
    int nf4 = nblocks >> 2;
    const float4* p4 = reinterpret_cast<const float4*>(g_partials);
    float s = 0.0f;
    for (int i = threadIdx.x; i < nf4; i += blockDim.x) {
        float4 v = p4[i];
        s += (v.x + v.y) + (v.z + v.w);
    }
    for (int i = (nf4 << 2) + threadIdx.x; i < nblocks; i += blockDim.x)
        s += g_partials[i];
#pragma unroll
    for (int o = 16; o > 0; o >>= 1)
        s += __shfl_down_sync(0xFFFFFFFFu, s, o);
    if ((threadIdx.x & 31) == 0)
        sm[threadIdx.x >> 5] = s;
    __syncthreads();
    if (threadIdx.x < 32) {
        s = (threadIdx.x < (int)(blockDim.x >> 5)) ? sm[threadIdx.x] : 0.0f;
#pragma unroll
        for (int o = 16; o > 0; o >>= 1)
            s += __shfl_down_sync(0xFFFFFFFFu, s, o);
        if (threadIdx.x == 0)
            out[0] = s * invN;
    }
}

extern "C" void kernel_launch(void* const* d_in, const int* in_sizes, int n_in,
                              void* d_out, int out_size) {
    const float* predict = (const float*)d_in[0];
    const float* label   = (const float*)d_in[1];
    float* out = (float*)d_out;

    int total  = in_sizes[0];          // B*7*7*26
    int ncells = total / 26;           // B*49
    int nblocks = (ncells + TPB - 1) / TPB;
    if (nblocks > MAX_BLOCKS) nblocks = MAX_BLOCKS;  // never hit for this shape

    float invN = 49.0f / (float)ncells;  // 1 / batch

    yolo_cell_kernel<<<nblocks, TPB>>>(predict, label, ncells);

    // Reduce kernel with programmatic dependent launch: launch setup overlaps
    // the producer's execution; cudaGridDependencySynchronize() inside the
    // kernel enforces ordering. Graph capture records the programmatic edge.
    cudaLaunchConfig_t cfg = {};
    cfg.gridDim  = dim3(1, 1, 1);
    cfg.blockDim = dim3(1024, 1, 1);
    cfg.dynamicSmemBytes = 0;
    cfg.stream = 0;
    cudaLaunchAttribute attr[1];
    attr[0].id = cudaLaunchAttributeProgrammaticStreamSerialization;
    attr[0].val.programmaticStreamSerializationAllowed = 1;
    cfg.attrs = attr;
    cfg.numAttrs = 1;
    cudaLaunchKernelEx(&cfg, yolo_reduce_kernel, out, nblocks, invN);
}